// round 13
// baseline (speedup 1.0000x reference)
#include <cuda_runtime.h>
#include <cuda_fp16.h>
#include <mma.h>
#include <cstddef>
#include <cstdint>

using namespace nvcuda;

#define BATCH 2
#define NSINK 1024
#define NSRC  4096
#define DIM   512          // sink_dim == src_dim == hid
#define HID   512
#define NH    8
#define HD    64           // head dim
#define LNEPS 1e-6f
#define ATTEPS 1e-6f

// ---------------- static scratch (no allocations allowed) ----------------
__device__ __half g_snorm_h[BATCH * NSINK * DIM];
__device__ __half g_cnorm_h[BATCH * NSRC  * DIM];
__device__ __half g_q_h   [BATCH * NSINK * HID];
__device__ __half g_kv_h  [BATCH * NSRC  * 2 * HID];
__device__ __half g_p_h   [(size_t)BATCH * NH * NSINK * NSRC];   // exp(sim), 128 MB
__device__ float  g_colz  [BATCH * NH * NSRC];                   // 1 / colsum
__device__ __half g_o_h   [BATCH * NSINK * HID];
__device__ __half g_wq_h  [DIM * HID];
__device__ __half g_wkv_h [DIM * 2 * HID];
__device__ __half g_wo_h  [HID * DIM];

// ---------------- cp.async helpers ----------------
__device__ __forceinline__ void cpa16(void* dst, const void* src) {
    uint32_t d = (uint32_t)__cvta_generic_to_shared(dst);
    asm volatile("cp.async.cg.shared.global [%0], [%1], 16;" :: "r"(d), "l"(src));
}
#define CP_COMMIT() asm volatile("cp.async.commit_group;")
#define CP_WAIT(n)  asm volatile("cp.async.wait_group %0;" :: "n"(n))

// ---------------- fused fp32 -> fp16 weight convert ----------------
__global__ __launch_bounds__(256) void cvt_all(
    const float* __restrict__ wq, const float* __restrict__ wkv,
    const float* __restrict__ wo, __half* __restrict__ dq,
    __half* __restrict__ dkv, __half* __restrict__ dwo)
{
    int i = blockIdx.x * 256 + threadIdx.x;           // total 1,048,576
    if (i < 262144)       dq[i]           = __float2half(wq[i]);
    else if (i < 786432)  dkv[i - 262144] = __float2half(wkv[i - 262144]);
    else                  dwo[i - 786432] = __float2half(wo[i - 786432]);
}

// ---------------- block reduction (deadlock-free) ----------------
template<int NT>
__device__ __forceinline__ float block_sum(float v) {
    __shared__ float sh[32];
    #pragma unroll
    for (int o = 16; o; o >>= 1) v += __shfl_xor_sync(0xffffffffu, v, o);
    if ((threadIdx.x & 31) == 0) sh[threadIdx.x >> 5] = v;
    __syncthreads();
    if (threadIdx.x < 32) {
        float x = (threadIdx.x < NT / 32) ? sh[threadIdx.x] : 0.f;
        #pragma unroll
        for (int o = 16; o; o >>= 1) x += __shfl_xor_sync(0xffffffffu, x, o);
        if (threadIdx.x == 0) sh[0] = x;
    }
    __syncthreads();
    v = sh[0];
    __syncthreads();
    return v;
}

// ---------------- LayerNorm -> fp16 output ----------------
__global__ __launch_bounds__(128) void ln_kernel(
    const float* __restrict__ x, const float* __restrict__ gamma,
    const float* __restrict__ beta, __half* __restrict__ y)
{
    const float* xr = x + (size_t)blockIdx.x * DIM;
    __half* yr = y + (size_t)blockIdx.x * DIM;
    float v[4];
    float s = 0.f;
    #pragma unroll
    for (int i = 0; i < 4; i++) { v[i] = xr[threadIdx.x + 128 * i]; s += v[i]; }
    float mu = block_sum<128>(s) * (1.f / DIM);
    float var = 0.f;
    #pragma unroll
    for (int i = 0; i < 4; i++) { float d = v[i] - mu; var += d * d; }
    var = block_sum<128>(var) * (1.f / DIM);
    float r = rsqrtf(var + LNEPS);
    #pragma unroll
    for (int i = 0; i < 4; i++) {
        int c = threadIdx.x + 128 * i;
        yr[c] = __float2half((v[i] - mu) * r * gamma[c] + beta[c]);
    }
}

// ======== pipelined wmma GEMM + bias: C = A_h @ B_h + bias ========
// 128x128 tile, 8 warps, k-step 32, 2-stage cp.async double buffering.
template<bool OUT_HALF>
__global__ __launch_bounds__(256) void gemm_wmma(
    const __half* __restrict__ A, const __half* __restrict__ B,
    const float* __restrict__ bias, void* __restrict__ Cv,
    int M, int N, int K)
{
    __shared__ __half As[2][128 * 40];
    __shared__ __half Bs[2][32 * 136];
    __shared__ float  stage[8][16 * 20];
    const int t = threadIdx.x, w = t >> 5, lane = t & 31;
    const int wr = w >> 1, wc = w & 1;
    const int i0 = blockIdx.y * 128, j0 = blockIdx.x * 128;

    auto load_tiles = [&](int kt, int s) {
        #pragma unroll
        for (int c = t; c < 512; c += 256) {           // A: 128x32
            int r = c >> 2, cc = (c & 3) << 3;
            cpa16(&As[s][r * 40 + cc], &A[(size_t)(i0 + r) * K + kt + cc]);
        }
        #pragma unroll
        for (int c = t; c < 512; c += 256) {           // B: 32x128
            int r = c >> 4, cc = (c & 15) << 3;
            cpa16(&Bs[s][r * 136 + cc], &B[(size_t)(kt + r) * N + j0 + cc]);
        }
    };

    wmma::fragment<wmma::accumulator, 16, 16, 16, float> acc[2][4];
    #pragma unroll
    for (int m = 0; m < 2; m++)
        #pragma unroll
        for (int n = 0; n < 4; n++) wmma::fill_fragment(acc[m][n], 0.f);

    load_tiles(0, 0);
    CP_COMMIT();
    int s = 0;
    for (int kt = 0; kt < K; kt += 32, s ^= 1) {
        if (kt + 32 < K) { load_tiles(kt + 32, s ^ 1); CP_COMMIT(); CP_WAIT(1); }
        else             { CP_WAIT(0); }
        __syncthreads();
        #pragma unroll
        for (int kk = 0; kk < 2; kk++) {
            wmma::fragment<wmma::matrix_a, 16, 16, 16, __half, wmma::row_major> af[2];
            wmma::fragment<wmma::matrix_b, 16, 16, 16, __half, wmma::row_major> bf[4];
            #pragma unroll
            for (int m = 0; m < 2; m++)
                wmma::load_matrix_sync(af[m], &As[s][(wr * 32 + m * 16) * 40 + kk * 16], 40);
            #pragma unroll
            for (int n = 0; n < 4; n++)
                wmma::load_matrix_sync(bf[n], &Bs[s][(kk * 16) * 136 + wc * 64 + n * 16], 136);
            #pragma unroll
            for (int m = 0; m < 2; m++)
                #pragma unroll
                for (int n = 0; n < 4; n++)
                    wmma::mma_sync(acc[m][n], af[m], bf[n], acc[m][n]);
        }
        __syncthreads();
    }
    #pragma unroll
    for (int m = 0; m < 2; m++)
        #pragma unroll
        for (int n = 0; n < 4; n++) {
            wmma::store_matrix_sync(stage[w], acc[m][n], 20, wmma::mem_row_major);
            __syncwarp();
            int row = lane >> 1, c0 = (lane & 1) << 3;
            int gi = i0 + wr * 32 + m * 16 + row;
            int gj = j0 + wc * 64 + n * 16 + c0;
            #pragma unroll
            for (int c = 0; c < 8; c++) {
                float vv = stage[w][row * 20 + c0 + c] + bias[gj + c];
                if (OUT_HALF) ((__half*)Cv)[(size_t)gi * N + gj + c] = __float2half(vv);
                else          ((float*)Cv)[(size_t)gi * N + gj + c] = vv;
            }
            __syncwarp();
        }
}

// ======== p = exp(scale * q kᵀ) per (b,h), fp16 out (max-free softmax) ========
__global__ __launch_bounds__(256) void sim_wmma(
    const __half* __restrict__ q, const __half* __restrict__ kv,
    __half* __restrict__ p)
{
    __shared__ __half As[128 * 72];
    __shared__ __half Bs[128 * 72];
    __shared__ float  stage[8][16 * 20];
    const int bh = blockIdx.z, b = bh / NH, h = bh % NH;
    const __half* A  = q  + (size_t)b * NSINK * HID + h * HD;
    const __half* Bk = kv + (size_t)b * NSRC * (2 * HID) + h * HD;
    __half* C = p + (size_t)bh * NSINK * NSRC;
    const int t = threadIdx.x, w = t >> 5, lane = t & 31;
    const int wr = w >> 1, wc = w & 1;
    const int i0 = blockIdx.y * 128, j0 = blockIdx.x * 128;

    #pragma unroll
    for (int c = t; c < 1024; c += 256) {
        int r = c >> 3, cc = (c & 7) << 3;
        cpa16(&As[r * 72 + cc], &A[(size_t)(i0 + r) * HID + cc]);
    }
    #pragma unroll
    for (int c = t; c < 1024; c += 256) {
        int r = c >> 3, cc = (c & 7) << 3;
        cpa16(&Bs[r * 72 + cc], &Bk[(size_t)(j0 + r) * (2 * HID) + cc]);
    }
    CP_COMMIT();
    CP_WAIT(0);
    __syncthreads();

    wmma::fragment<wmma::accumulator, 16, 16, 16, float> acc[2][4];
    #pragma unroll
    for (int m = 0; m < 2; m++)
        #pragma unroll
        for (int n = 0; n < 4; n++) wmma::fill_fragment(acc[m][n], 0.f);
    #pragma unroll
    for (int kk = 0; kk < 4; kk++) {
        wmma::fragment<wmma::matrix_a, 16, 16, 16, __half, wmma::row_major> af[2];
        wmma::fragment<wmma::matrix_b, 16, 16, 16, __half, wmma::col_major> bf[4];
        #pragma unroll
        for (int m = 0; m < 2; m++)
            wmma::load_matrix_sync(af[m], &As[(wr * 32 + m * 16) * 72 + kk * 16], 72);
        #pragma unroll
        for (int n = 0; n < 4; n++)
            wmma::load_matrix_sync(bf[n], &Bs[(wc * 64 + n * 16) * 72 + kk * 16], 72);
        #pragma unroll
        for (int m = 0; m < 2; m++)
            #pragma unroll
            for (int n = 0; n < 4; n++)
                wmma::mma_sync(acc[m][n], af[m], bf[n], acc[m][n]);
    }
    #pragma unroll
    for (int m = 0; m < 2; m++)
        #pragma unroll
        for (int n = 0; n < 4; n++) {
            wmma::store_matrix_sync(stage[w], acc[m][n], 20, wmma::mem_row_major);
            __syncwarp();
            int row = lane >> 1, c0 = (lane & 1) << 3;
            int gi = i0 + wr * 32 + m * 16 + row;
            int gj = j0 + wc * 64 + n * 16 + c0;
            #pragma unroll
            for (int c = 0; c < 8; c++)
                C[(size_t)gi * NSRC + gj + c] =
                    __float2half(__expf(stage[w][row * 20 + c0 + c] * 0.125f));
            __syncwarp();
        }
}

// ======== colsum: z_j = sum_i p_ij ; store 1/z (pure bandwidth) ========
__global__ __launch_bounds__(256) void colsum_h(
    const __half* __restrict__ p, float* __restrict__ colz)
{
    const int bh = blockIdx.y;
    const int j = blockIdx.x * 512 + threadIdx.x * 2;
    const __half* P = p + (size_t)bh * NSINK * NSRC + j;
    float2 z0 = {0.f, 0.f}, z1 = {0.f, 0.f}, z2 = {0.f, 0.f}, z3 = {0.f, 0.f};
    #pragma unroll 1
    for (int i = 0; i < NSINK; i += 4) {
        float2 a = __half22float2(*(const __half2*)&P[(size_t)(i + 0) * NSRC]);
        float2 b = __half22float2(*(const __half2*)&P[(size_t)(i + 1) * NSRC]);
        float2 c = __half22float2(*(const __half2*)&P[(size_t)(i + 2) * NSRC]);
        float2 d = __half22float2(*(const __half2*)&P[(size_t)(i + 3) * NSRC]);
        z0.x += a.x; z0.y += a.y;
        z1.x += b.x; z1.y += b.y;
        z2.x += c.x; z2.y += c.y;
        z3.x += d.x; z3.y += d.y;
    }
    colz[bh * NSRC + j]     = 1.f / (z0.x + z1.x + z2.x + z3.x);
    colz[bh * NSRC + j + 1] = 1.f / (z0.y + z1.y + z2.y + z3.y);
}

// ======== out = (attn @ V_ext) / rowsum; 2-stage cp.async pipeline ========
// Raw p loaded async, transformed in place (p*invz + eps). Ones col -> rowsum.
__global__ __launch_bounds__(128) void av_wmma(
    const __half* __restrict__ p, const __half* __restrict__ kv,
    const float* __restrict__ colz, __half* __restrict__ o)
{
    __shared__ __half As[2][64 * 72];   // raw p -> attn, ld 72
    __shared__ __half Bs[2][64 * 88];   // V_ext, ld 88
    __shared__ float  stage[4][16 * 20];
    __shared__ float  rs[4][16];
    const int bh = blockIdx.z, b = bh / NH, h = bh % NH;
    const __half* A = p + (size_t)bh * NSINK * NSRC;
    const __half* V = kv + (size_t)b * NSRC * (2 * HID) + HID + h * HD;
    const float* cz = colz + bh * NSRC;
    const int t = threadIdx.x, w = t >> 5, lane = t & 31;
    const int i0 = blockIdx.y * 64;

    // fill ones-column extension (cols 64..87) of both buffers once
    #pragma unroll
    for (int e = t; e < 64 * 24; e += 128) {
        int r = e / 24, cc = 64 + e % 24;
        __half v = __float2half(cc == 64 ? 1.f : 0.f);
        Bs[0][r * 88 + cc] = v;
        Bs[1][r * 88 + cc] = v;
    }
    __syncthreads();

    auto load_tiles = [&](int kt, int s) {
        #pragma unroll
        for (int e = t; e < 512; e += 128) {           // p: 64x64
            int r = e >> 3, cc = (e & 7) << 3;
            cpa16(&As[s][r * 72 + cc], &A[(size_t)(i0 + r) * NSRC + kt + cc]);
        }
        #pragma unroll
        for (int e = t; e < 512; e += 128) {           // V: 64x64
            int r = e >> 3, cc = (e & 7) << 3;
            cpa16(&Bs[s][r * 88 + cc], &V[(size_t)(kt + r) * (2 * HID) + cc]);
        }
    };

    wmma::fragment<wmma::accumulator, 16, 16, 16, float> acc[5];
    #pragma unroll
    for (int n = 0; n < 5; n++) wmma::fill_fragment(acc[n], 0.f);

    load_tiles(0, 0);
    CP_COMMIT();
    int s = 0;
    for (int kt = 0; kt < NSRC; kt += 64, s ^= 1) {
        if (kt + 64 < NSRC) { load_tiles(kt + 64, s ^ 1); CP_COMMIT(); CP_WAIT(1); }
        else                { CP_WAIT(0); }
        __syncthreads();
        // transform raw p -> attn in place: p * invz + eps
        #pragma unroll
        for (int e = t; e < 2048; e += 128) {
            int r = e >> 5, c2 = e & 31;
            int j = kt + c2 * 2;
            float2 pf = __half22float2(*(__half2*)&As[s][r * 72 + c2 * 2]);
            float2 zf = *(const float2*)&cz[j];
            *(__half2*)&As[s][r * 72 + c2 * 2] =
                __floats2half2_rn(pf.x * zf.x + ATTEPS, pf.y * zf.y + ATTEPS);
        }
        __syncthreads();
        #pragma unroll
        for (int kk = 0; kk < 4; kk++) {
            wmma::fragment<wmma::matrix_a, 16, 16, 16, __half, wmma::row_major> af;
            wmma::load_matrix_sync(af, &As[s][(w * 16) * 72 + kk * 16], 72);
            #pragma unroll
            for (int n = 0; n < 5; n++) {
                wmma::fragment<wmma::matrix_b, 16, 16, 16, __half, wmma::row_major> bf;
                wmma::load_matrix_sync(bf, &Bs[s][(kk * 16) * 88 + n * 16], 88);
                wmma::mma_sync(acc[n], af, bf, acc[n]);
            }
        }
        __syncthreads();   // mma reads done before next prefetch overwrites buf s
    }
    wmma::store_matrix_sync(stage[w], acc[4], 20, wmma::mem_row_major);
    __syncwarp();
    if (lane < 16) rs[w][lane] = 1.f / stage[w][lane * 20 + 0];
    __syncwarp();
    #pragma unroll
    for (int n = 0; n < 4; n++) {
        wmma::store_matrix_sync(stage[w], acc[n], 20, wmma::mem_row_major);
        __syncwarp();
        int row = lane >> 1, c0 = (lane & 1) << 3;
        int gi = i0 + w * 16 + row;
        #pragma unroll
        for (int c = 0; c < 8; c++)
            o[(size_t)(b * NSINK + gi) * HID + h * HD + n * 16 + c0 + c] =
                __float2half(stage[w][row * 20 + c0 + c] * rs[w][row]);
        __syncwarp();
    }
}

// ---------------- launch ----------------
extern "C" void kernel_launch(void* const* d_in, const int* in_sizes, int n_in,
                              void* d_out, int out_size)
{
    const float* sink    = (const float*)d_in[0];
    const float* source  = (const float*)d_in[1];
    const float* gamma_s = (const float*)d_in[2];
    const float* beta_s  = (const float*)d_in[3];
    const float* gamma_c = (const float*)d_in[4];
    const float* beta_c  = (const float*)d_in[5];
    const float* Wq      = (const float*)d_in[6];
    const float* bq      = (const float*)d_in[7];
    const float* Wkv     = (const float*)d_in[8];
    const float* bkv     = (const float*)d_in[9];
    const float* Wo      = (const float*)d_in[10];
    const float* bo      = (const float*)d_in[11];
    float* out = (float*)d_out;

    __half *snorm_h, *cnorm_h, *q_h, *kv_h, *p_h, *o_h, *wq_h, *wkv_h, *wo_h;
    float *colz;
    cudaGetSymbolAddress((void**)&snorm_h, g_snorm_h);
    cudaGetSymbolAddress((void**)&cnorm_h, g_cnorm_h);
    cudaGetSymbolAddress((void**)&q_h,     g_q_h);
    cudaGetSymbolAddress((void**)&kv_h,    g_kv_h);
    cudaGetSymbolAddress((void**)&p_h,     g_p_h);
    cudaGetSymbolAddress((void**)&colz,    g_colz);
    cudaGetSymbolAddress((void**)&o_h,     g_o_h);
    cudaGetSymbolAddress((void**)&wq_h,    g_wq_h);
    cudaGetSymbolAddress((void**)&wkv_h,   g_wkv_h);
    cudaGetSymbolAddress((void**)&wo_h,    g_wo_h);

    // 0. fused weight conversion (1 launch -> ncu -s 5 lands on sim_wmma)
    cvt_all<<<4096, 256>>>(Wq, Wkv, Wo, wq_h, wkv_h, wo_h);

    // 1. pre-norms (fp16 out)
    ln_kernel<<<BATCH * NSINK, 128>>>(sink, gamma_s, beta_s, snorm_h);
    ln_kernel<<<BATCH * NSRC, 128>>>(source, gamma_c, beta_c, cnorm_h);

    // 2. projections (pipelined tensor cores)
    gemm_wmma<true><<<dim3(HID / 128, BATCH * NSINK / 128), 256>>>(
        snorm_h, wq_h, bq, q_h, BATCH * NSINK, HID, DIM);
    gemm_wmma<true><<<dim3(2 * HID / 128, BATCH * NSRC / 128), 256>>>(
        cnorm_h, wkv_h, bkv, kv_h, BATCH * NSRC, 2 * HID, DIM);

    // 3. p = exp(scale * q kᵀ)  (max-free; |sim| small by construction)
    sim_wmma<<<dim3(NSRC / 128, NSINK / 128, BATCH * NH), 256>>>(q_h, kv_h, p_h);

    // 4. column sums -> 1/z
    colsum_h<<<dim3(NSRC / 512, BATCH * NH), 256>>>(p_h, colz);

    // 5. AV with fused renorm (pipelined), 256 blocks
    av_wmma<<<dim3(1, NSINK / 64, BATCH * NH), 128>>>(p_h, kv_h, colz, o_h);

    // 6. output projection (fp32 out)
    gemm_wmma<false><<<dim3(DIM / 128, BATCH * NSINK / 128), 256>>>(
        o_h, wo_h, bo, out, BATCH * NSINK, DIM, DIM);
}

// round 14
// speedup vs baseline: 1.0350x; 1.0350x over previous
#include <cuda_runtime.h>
#include <cuda_fp16.h>
#include <mma.h>
#include <cstddef>
#include <cstdint>

using namespace nvcuda;

#define BATCH 2
#define NSINK 1024
#define NSRC  4096
#define DIM   512          // sink_dim == src_dim == hid
#define HID   512
#define NH    8
#define HD    64           // head dim
#define LNEPS 1e-6f
#define ATTEPS 1e-6f

// ---------------- static scratch (no allocations allowed) ----------------
__device__ __half g_snorm_h[BATCH * NSINK * DIM];
__device__ __half g_cnorm_h[BATCH * NSRC  * DIM];
__device__ __half g_q_h   [BATCH * NSINK * HID];
__device__ __half g_kv_h  [BATCH * NSRC  * 2 * HID];
__device__ __half g_p_h   [(size_t)BATCH * NH * NSINK * NSRC];   // exp(sim), 128 MB
__device__ float  g_colz  [BATCH * NH * NSRC];                   // 1 / colsum
__device__ __half g_o_h   [BATCH * NSINK * HID];
__device__ __half g_wq_h  [DIM * HID];
__device__ __half g_wkv_h [DIM * 2 * HID];
__device__ __half g_wo_h  [HID * DIM];

// ---------------- fused fp32 -> fp16 weight convert ----------------
__global__ __launch_bounds__(256) void cvt_all(
    const float* __restrict__ wq, const float* __restrict__ wkv,
    const float* __restrict__ wo, __half* __restrict__ dq,
    __half* __restrict__ dkv, __half* __restrict__ dwo)
{
    int i = blockIdx.x * 256 + threadIdx.x;           // total 1,048,576
    if (i < 262144)       dq[i]           = __float2half(wq[i]);
    else if (i < 786432)  dkv[i - 262144] = __float2half(wkv[i - 262144]);
    else                  dwo[i - 786432] = __float2half(wo[i - 786432]);
}

// ---------------- block reduction (deadlock-free) ----------------
template<int NT>
__device__ __forceinline__ float block_sum(float v) {
    __shared__ float sh[32];
    #pragma unroll
    for (int o = 16; o; o >>= 1) v += __shfl_xor_sync(0xffffffffu, v, o);
    if ((threadIdx.x & 31) == 0) sh[threadIdx.x >> 5] = v;
    __syncthreads();
    if (threadIdx.x < 32) {
        float x = (threadIdx.x < NT / 32) ? sh[threadIdx.x] : 0.f;
        #pragma unroll
        for (int o = 16; o; o >>= 1) x += __shfl_xor_sync(0xffffffffu, x, o);
        if (threadIdx.x == 0) sh[0] = x;
    }
    __syncthreads();
    v = sh[0];
    __syncthreads();
    return v;
}

// ---------------- LayerNorm -> fp16 output ----------------
__global__ __launch_bounds__(128) void ln_kernel(
    const float* __restrict__ x, const float* __restrict__ gamma,
    const float* __restrict__ beta, __half* __restrict__ y)
{
    const float* xr = x + (size_t)blockIdx.x * DIM;
    __half* yr = y + (size_t)blockIdx.x * DIM;
    float v[4];
    float s = 0.f;
    #pragma unroll
    for (int i = 0; i < 4; i++) { v[i] = xr[threadIdx.x + 128 * i]; s += v[i]; }
    float mu = block_sum<128>(s) * (1.f / DIM);
    float var = 0.f;
    #pragma unroll
    for (int i = 0; i < 4; i++) { float d = v[i] - mu; var += d * d; }
    var = block_sum<128>(var) * (1.f / DIM);
    float r = rsqrtf(var + LNEPS);
    #pragma unroll
    for (int i = 0; i < 4; i++) {
        int c = threadIdx.x + 128 * i;
        yr[c] = __float2half((v[i] - mu) * r * gamma[c] + beta[c]);
    }
}

// ======== wmma GEMM 128x128, 8 warps, 2 blocks/SM (for the big KV proj) ====
template<bool OUT_HALF>
__global__ __launch_bounds__(256, 2) void gemm_wmma(
    const __half* __restrict__ A, const __half* __restrict__ B,
    const float* __restrict__ bias, void* __restrict__ Cv,
    int M, int N, int K)
{
    __shared__ __half As[128 * 40];
    __shared__ __half Bs[32 * 136];
    __shared__ float  stage[8][16 * 20];
    const int t = threadIdx.x, w = t >> 5, lane = t & 31;
    const int wr = w >> 1, wc = w & 1;
    const int i0 = blockIdx.y * 128, j0 = blockIdx.x * 128;
    wmma::fragment<wmma::accumulator, 16, 16, 16, float> acc[2][4];
    #pragma unroll
    for (int m = 0; m < 2; m++)
        #pragma unroll
        for (int n = 0; n < 4; n++) wmma::fill_fragment(acc[m][n], 0.f);

    for (int kt = 0; kt < K; kt += 32) {
        #pragma unroll
        for (int c = t; c < 512; c += 256) {
            int r = c >> 2, cc = (c & 3) << 3;
            *(uint4*)&As[r * 40 + cc] = *(const uint4*)&A[(size_t)(i0 + r) * K + kt + cc];
        }
        #pragma unroll
        for (int c = t; c < 512; c += 256) {
            int r = c >> 4, cc = (c & 15) << 3;
            *(uint4*)&Bs[r * 136 + cc] = *(const uint4*)&B[(size_t)(kt + r) * N + j0 + cc];
        }
        __syncthreads();
        #pragma unroll
        for (int kk = 0; kk < 2; kk++) {
            wmma::fragment<wmma::matrix_a, 16, 16, 16, __half, wmma::row_major> af[2];
            wmma::fragment<wmma::matrix_b, 16, 16, 16, __half, wmma::row_major> bf[4];
            #pragma unroll
            for (int m = 0; m < 2; m++)
                wmma::load_matrix_sync(af[m], &As[(wr * 32 + m * 16) * 40 + kk * 16], 40);
            #pragma unroll
            for (int n = 0; n < 4; n++)
                wmma::load_matrix_sync(bf[n], &Bs[(kk * 16) * 136 + wc * 64 + n * 16], 136);
            #pragma unroll
            for (int m = 0; m < 2; m++)
                #pragma unroll
                for (int n = 0; n < 4; n++)
                    wmma::mma_sync(acc[m][n], af[m], bf[n], acc[m][n]);
        }
        __syncthreads();
    }
    #pragma unroll
    for (int m = 0; m < 2; m++)
        #pragma unroll
        for (int n = 0; n < 4; n++) {
            wmma::store_matrix_sync(stage[w], acc[m][n], 20, wmma::mem_row_major);
            __syncwarp();
            int row = lane >> 1, c0 = (lane & 1) << 3;
            int gi = i0 + wr * 32 + m * 16 + row;
            int gj = j0 + wc * 64 + n * 16 + c0;
            #pragma unroll
            for (int c = 0; c < 8; c++) {
                float vv = stage[w][row * 20 + c0 + c] + bias[gj + c];
                if (OUT_HALF) ((__half*)Cv)[(size_t)gi * N + gj + c] = __float2half(vv);
                else          ((float*)Cv)[(size_t)gi * N + gj + c] = vv;
            }
            __syncwarp();
        }
}

// ======== wmma GEMM 64x64, 4 warps — full-chip coverage for Q/O proj ======
template<bool OUT_HALF>
__global__ __launch_bounds__(128, 4) void gemm64_wmma(
    const __half* __restrict__ A, const __half* __restrict__ B,
    const float* __restrict__ bias, void* __restrict__ Cv,
    int M, int N, int K)
{
    __shared__ __half As[64 * 40];     // [row][k] ld 40
    __shared__ __half Bs[32 * 72];     // [k][col] ld 72
    __shared__ float  stage[4][16 * 20];
    const int t = threadIdx.x, w = t >> 5, lane = t & 31;
    const int wr = w >> 1, wc = w & 1;
    const int i0 = blockIdx.y * 64, j0 = blockIdx.x * 64;
    wmma::fragment<wmma::accumulator, 16, 16, 16, float> acc[2][2];
    #pragma unroll
    for (int m = 0; m < 2; m++)
        #pragma unroll
        for (int n = 0; n < 2; n++) wmma::fill_fragment(acc[m][n], 0.f);

    for (int kt = 0; kt < K; kt += 32) {
        #pragma unroll
        for (int c = t; c < 256; c += 128) {           // A: 64x32
            int r = c >> 2, cc = (c & 3) << 3;
            *(uint4*)&As[r * 40 + cc] = *(const uint4*)&A[(size_t)(i0 + r) * K + kt + cc];
        }
        #pragma unroll
        for (int c = t; c < 256; c += 128) {           // B: 32x64
            int r = c >> 3, cc = (c & 7) << 3;
            *(uint4*)&Bs[r * 72 + cc] = *(const uint4*)&B[(size_t)(kt + r) * N + j0 + cc];
        }
        __syncthreads();
        #pragma unroll
        for (int kk = 0; kk < 2; kk++) {
            wmma::fragment<wmma::matrix_a, 16, 16, 16, __half, wmma::row_major> af[2];
            wmma::fragment<wmma::matrix_b, 16, 16, 16, __half, wmma::row_major> bf[2];
            #pragma unroll
            for (int m = 0; m < 2; m++)
                wmma::load_matrix_sync(af[m], &As[(wr * 32 + m * 16) * 40 + kk * 16], 40);
            #pragma unroll
            for (int n = 0; n < 2; n++)
                wmma::load_matrix_sync(bf[n], &Bs[(kk * 16) * 72 + wc * 32 + n * 16], 72);
            #pragma unroll
            for (int m = 0; m < 2; m++)
                #pragma unroll
                for (int n = 0; n < 2; n++)
                    wmma::mma_sync(acc[m][n], af[m], bf[n], acc[m][n]);
        }
        __syncthreads();
    }
    #pragma unroll
    for (int m = 0; m < 2; m++)
        #pragma unroll
        for (int n = 0; n < 2; n++) {
            wmma::store_matrix_sync(stage[w], acc[m][n], 20, wmma::mem_row_major);
            __syncwarp();
            int row = lane >> 1, c0 = (lane & 1) << 3;
            int gi = i0 + wr * 32 + m * 16 + row;
            int gj = j0 + wc * 32 + n * 16 + c0;
            #pragma unroll
            for (int c = 0; c < 8; c++) {
                float vv = stage[w][row * 20 + c0 + c] + bias[gj + c];
                if (OUT_HALF) ((__half*)Cv)[(size_t)gi * N + gj + c] = __float2half(vv);
                else          ((float*)Cv)[(size_t)gi * N + gj + c] = vv;
            }
            __syncwarp();
        }
}

// ======== p = exp(scale * q kᵀ) per (b,h), fp16 out (max-free softmax) ======
__global__ __launch_bounds__(256, 2) void sim_wmma(
    const __half* __restrict__ q, const __half* __restrict__ kv,
    __half* __restrict__ p)
{
    __shared__ __half As[128 * 72];
    __shared__ __half Bs[128 * 72];
    __shared__ float  stage[8][16 * 20];
    const int bh = blockIdx.z, b = bh / NH, h = bh % NH;
    const __half* A  = q  + (size_t)b * NSINK * HID + h * HD;
    const __half* Bk = kv + (size_t)b * NSRC * (2 * HID) + h * HD;
    __half* C = p + (size_t)bh * NSINK * NSRC;
    const int t = threadIdx.x, w = t >> 5, lane = t & 31;
    const int wr = w >> 1, wc = w & 1;
    const int i0 = blockIdx.y * 128, j0 = blockIdx.x * 128;

    #pragma unroll
    for (int c = t; c < 1024; c += 256) {
        int r = c >> 3, cc = (c & 7) << 3;
        *(uint4*)&As[r * 72 + cc] = *(const uint4*)&A[(size_t)(i0 + r) * HID + cc];
    }
    #pragma unroll
    for (int c = t; c < 1024; c += 256) {
        int r = c >> 3, cc = (c & 7) << 3;
        *(uint4*)&Bs[r * 72 + cc] = *(const uint4*)&Bk[(size_t)(j0 + r) * (2 * HID) + cc];
    }
    __syncthreads();

    wmma::fragment<wmma::accumulator, 16, 16, 16, float> acc[2][4];
    #pragma unroll
    for (int m = 0; m < 2; m++)
        #pragma unroll
        for (int n = 0; n < 4; n++) wmma::fill_fragment(acc[m][n], 0.f);
    #pragma unroll
    for (int kk = 0; kk < 4; kk++) {
        wmma::fragment<wmma::matrix_a, 16, 16, 16, __half, wmma::row_major> af[2];
        wmma::fragment<wmma::matrix_b, 16, 16, 16, __half, wmma::col_major> bf[4];
        #pragma unroll
        for (int m = 0; m < 2; m++)
            wmma::load_matrix_sync(af[m], &As[(wr * 32 + m * 16) * 72 + kk * 16], 72);
        #pragma unroll
        for (int n = 0; n < 4; n++)
            wmma::load_matrix_sync(bf[n], &Bs[(wc * 64 + n * 16) * 72 + kk * 16], 72);
        #pragma unroll
        for (int m = 0; m < 2; m++)
            #pragma unroll
            for (int n = 0; n < 4; n++)
                wmma::mma_sync(acc[m][n], af[m], bf[n], acc[m][n]);
    }
    #pragma unroll
    for (int m = 0; m < 2; m++)
        #pragma unroll
        for (int n = 0; n < 4; n++) {
            wmma::store_matrix_sync(stage[w], acc[m][n], 20, wmma::mem_row_major);
            __syncwarp();
            int row = lane >> 1, c0 = (lane & 1) << 3;
            int gi = i0 + wr * 32 + m * 16 + row;
            int gj = j0 + wc * 64 + n * 16 + c0;
            #pragma unroll
            for (int c = 0; c < 8; c++)
                C[(size_t)gi * NSRC + gj + c] =
                    __float2half(__expf(stage[w][row * 20 + c0 + c] * 0.125f));
            __syncwarp();
        }
}

// ======== colsum: z_j = sum_i p_ij ; store 1/z (pure bandwidth) ========
__global__ __launch_bounds__(256) void colsum_h(
    const __half* __restrict__ p, float* __restrict__ colz)
{
    const int bh = blockIdx.y;
    const int j = blockIdx.x * 512 + threadIdx.x * 2;
    const __half* P = p + (size_t)bh * NSINK * NSRC + j;
    float2 z0 = {0.f, 0.f}, z1 = {0.f, 0.f}, z2 = {0.f, 0.f}, z3 = {0.f, 0.f};
    #pragma unroll 1
    for (int i = 0; i < NSINK; i += 4) {
        float2 a = __half22float2(*(const __half2*)&P[(size_t)(i + 0) * NSRC]);
        float2 b = __half22float2(*(const __half2*)&P[(size_t)(i + 1) * NSRC]);
        float2 c = __half22float2(*(const __half2*)&P[(size_t)(i + 2) * NSRC]);
        float2 d = __half22float2(*(const __half2*)&P[(size_t)(i + 3) * NSRC]);
        z0.x += a.x; z0.y += a.y;
        z1.x += b.x; z1.y += b.y;
        z2.x += c.x; z2.y += c.y;
        z3.x += d.x; z3.y += d.y;
    }
    colz[bh * NSRC + j]     = 1.f / (z0.x + z1.x + z2.x + z3.x);
    colz[bh * NSRC + j + 1] = 1.f / (z0.y + z1.y + z2.y + z3.y);
}

// ======== out = (attn @ V_ext) / rowsum; attn = p*invz + eps (no exp) ========
__global__ __launch_bounds__(128, 3) void av_wmma(
    const __half* __restrict__ p, const __half* __restrict__ kv,
    const float* __restrict__ colz, __half* __restrict__ o)
{
    __shared__ __half As[64 * 72];     // attn [i][j64] ld 72
    __shared__ __half Bs[64 * 88];     // V_ext [j][88] ld 88
    __shared__ float  stage[4][16 * 20];
    __shared__ float  rs[4][16];
    const int bh = blockIdx.z, b = bh / NH, h = bh % NH;
    const __half* A = p + (size_t)bh * NSINK * NSRC;
    const __half* V = kv + (size_t)b * NSRC * (2 * HID) + HID + h * HD;
    const float* cz = colz + bh * NSRC;
    const int t = threadIdx.x, w = t >> 5, lane = t & 31;
    const int i0 = blockIdx.y * 64;

    wmma::fragment<wmma::accumulator, 16, 16, 16, float> acc[5];
    #pragma unroll
    for (int n = 0; n < 5; n++) wmma::fill_fragment(acc[n], 0.f);

    for (int kt = 0; kt < NSRC; kt += 64) {
        #pragma unroll
        for (int e = t; e < 2048; e += 128) {
            int r = e >> 5, c2 = e & 31;
            int j = kt + c2 * 2;
            float2 pf = __half22float2(*(const __half2*)&A[(size_t)(i0 + r) * NSRC + j]);
            float2 zf = *(const float2*)&cz[j];
            *(__half2*)&As[r * 72 + c2 * 2] =
                __floats2half2_rn(pf.x * zf.x + ATTEPS, pf.y * zf.y + ATTEPS);
        }
        #pragma unroll
        for (int c = t; c < 512; c += 128) {
            int r = c >> 3, cc = (c & 7) << 3;
            *(uint4*)&Bs[r * 88 + cc] = *(const uint4*)&V[(size_t)(kt + r) * (2 * HID) + cc];
        }
        #pragma unroll
        for (int e = t; e < 64 * 24; e += 128) {
            int r = e / 24, cc = 64 + e % 24;
            Bs[r * 88 + cc] = __float2half(cc == 64 ? 1.f : 0.f);
        }
        __syncthreads();
        #pragma unroll
        for (int kk = 0; kk < 4; kk++) {
            wmma::fragment<wmma::matrix_a, 16, 16, 16, __half, wmma::row_major> af;
            wmma::load_matrix_sync(af, &As[(w * 16) * 72 + kk * 16], 72);
            #pragma unroll
            for (int n = 0; n < 5; n++) {
                wmma::fragment<wmma::matrix_b, 16, 16, 16, __half, wmma::row_major> bf;
                wmma::load_matrix_sync(bf, &Bs[(kk * 16) * 88 + n * 16], 88);
                wmma::mma_sync(acc[n], af, bf, acc[n]);
            }
        }
        __syncthreads();
    }
    wmma::store_matrix_sync(stage[w], acc[4], 20, wmma::mem_row_major);
    __syncwarp();
    if (lane < 16) rs[w][lane] = 1.f / stage[w][lane * 20 + 0];
    __syncwarp();
    #pragma unroll
    for (int n = 0; n < 4; n++) {
        wmma::store_matrix_sync(stage[w], acc[n], 20, wmma::mem_row_major);
        __syncwarp();
        int row = lane >> 1, c0 = (lane & 1) << 3;
        int gi = i0 + w * 16 + row;
        #pragma unroll
        for (int c = 0; c < 8; c++)
            o[(size_t)(b * NSINK + gi) * HID + h * HD + n * 16 + c0 + c] =
                __float2half(stage[w][row * 20 + c0 + c] * rs[w][row]);
        __syncwarp();
    }
}

// ---------------- launch ----------------
extern "C" void kernel_launch(void* const* d_in, const int* in_sizes, int n_in,
                              void* d_out, int out_size)
{
    const float* sink    = (const float*)d_in[0];
    const float* source  = (const float*)d_in[1];
    const float* gamma_s = (const float*)d_in[2];
    const float* beta_s  = (const float*)d_in[3];
    const float* gamma_c = (const float*)d_in[4];
    const float* beta_c  = (const float*)d_in[5];
    const float* Wq      = (const float*)d_in[6];
    const float* bq      = (const float*)d_in[7];
    const float* Wkv     = (const float*)d_in[8];
    const float* bkv     = (const float*)d_in[9];
    const float* Wo      = (const float*)d_in[10];
    const float* bo      = (const float*)d_in[11];
    float* out = (float*)d_out;

    __half *snorm_h, *cnorm_h, *q_h, *kv_h, *p_h, *o_h, *wq_h, *wkv_h, *wo_h;
    float *colz;
    cudaGetSymbolAddress((void**)&snorm_h, g_snorm_h);
    cudaGetSymbolAddress((void**)&cnorm_h, g_cnorm_h);
    cudaGetSymbolAddress((void**)&q_h,     g_q_h);
    cudaGetSymbolAddress((void**)&kv_h,    g_kv_h);
    cudaGetSymbolAddress((void**)&p_h,     g_p_h);
    cudaGetSymbolAddress((void**)&colz,    g_colz);
    cudaGetSymbolAddress((void**)&o_h,     g_o_h);
    cudaGetSymbolAddress((void**)&wq_h,    g_wq_h);
    cudaGetSymbolAddress((void**)&wkv_h,   g_wkv_h);
    cudaGetSymbolAddress((void**)&wo_h,    g_wo_h);

    // 0. fused weight conversion
    cvt_all<<<4096, 256>>>(Wq, Wkv, Wo, wq_h, wkv_h, wo_h);

    // 1. pre-norms (fp16 out)
    ln_kernel<<<BATCH * NSINK, 128>>>(sink, gamma_s, beta_s, snorm_h);
    ln_kernel<<<BATCH * NSRC, 128>>>(source, gamma_c, beta_c, cnorm_h);

    // 2. projections: Q on 64x64 tiles (256 blocks), KV on 128x128 (512 blocks)
    gemm64_wmma<true><<<dim3(HID / 64, BATCH * NSINK / 64), 128>>>(
        snorm_h, wq_h, bq, q_h, BATCH * NSINK, HID, DIM);
    gemm_wmma<true><<<dim3(2 * HID / 128, BATCH * NSRC / 128), 256>>>(
        cnorm_h, wkv_h, bkv, kv_h, BATCH * NSRC, 2 * HID, DIM);

    // 3. p = exp(scale * q kᵀ)
    sim_wmma<<<dim3(NSRC / 128, NSINK / 128, BATCH * NH), 256>>>(q_h, kv_h, p_h);

    // 4. column sums -> 1/z
    colsum_h<<<dim3(NSRC / 512, BATCH * NH), 256>>>(p_h, colz);

    // 5. AV with fused renorm, 256 blocks, 3 blocks/SM allowed
    av_wmma<<<dim3(1, NSINK / 64, BATCH * NH), 128>>>(p_h, kv_h, colz, o_h);

    // 6. output projection on 64x64 tiles (256 blocks, fp32 out)
    gemm64_wmma<false><<<dim3(DIM / 64, BATCH * NSINK / 64), 128>>>(
        o_h, wo_h, bo, out, BATCH * NSINK, DIM, DIM);
}

// round 16
// speedup vs baseline: 1.2684x; 1.2256x over previous
#include <cuda_runtime.h>
#include <cuda_fp16.h>
#include <mma.h>
#include <cstddef>
#include <cstdint>

using namespace nvcuda;

#define BATCH 2
#define NSINK 1024
#define NSRC  4096
#define DIM   512          // sink_dim == src_dim == hid
#define HID   512
#define NH    8
#define HD    64           // head dim
#define LNEPS 1e-6f
#define ATTEPS 1e-6f
#define JCHUNKS 4          // av split-j factor
#define ICHUNKS 4          // colsum split-i factor

// ---------------- static scratch (no allocations allowed) ----------------
__device__ __half g_snorm_h[BATCH * NSINK * DIM];
__device__ __half g_cnorm_h[BATCH * NSRC  * DIM];
__device__ __half g_q_h   [BATCH * NSINK * HID];
__device__ __half g_kv_h  [BATCH * NSRC  * 2 * HID];
__device__ __half g_p_h   [(size_t)BATCH * NH * NSINK * NSRC];   // exp(sim), 128 MB
__device__ float  g_zpart [BATCH * NH * ICHUNKS * NSRC];         // colsum partials
__device__ float  g_colz  [BATCH * NH * NSRC];                   // 1 / colsum
__device__ float  g_opart [(size_t)JCHUNKS * BATCH * NSINK * HID]; // 16.8 MB
__device__ float  g_rspart[JCHUNKS * BATCH * NH * NSINK];        // rowsum partials
__device__ __half g_o_h   [BATCH * NSINK * HID];
__device__ __half g_wq_h  [DIM * HID];
__device__ __half g_wkv_h [DIM * 2 * HID];
__device__ __half g_wo_h  [HID * DIM];

// ---------------- fused fp32 -> fp16 weight convert ----------------
__global__ __launch_bounds__(256) void cvt_all(
    const float* __restrict__ wq, const float* __restrict__ wkv,
    const float* __restrict__ wo, __half* __restrict__ dq,
    __half* __restrict__ dkv, __half* __restrict__ dwo)
{
    int i = blockIdx.x * 256 + threadIdx.x;           // total 1,048,576
    if (i < 262144)       dq[i]           = __float2half(wq[i]);
    else if (i < 786432)  dkv[i - 262144] = __float2half(wkv[i - 262144]);
    else                  dwo[i - 786432] = __float2half(wo[i - 786432]);
}

// ---------------- block reduction (deadlock-free) ----------------
template<int NT>
__device__ __forceinline__ float block_sum(float v) {
    __shared__ float sh[32];
    #pragma unroll
    for (int o = 16; o; o >>= 1) v += __shfl_xor_sync(0xffffffffu, v, o);
    if ((threadIdx.x & 31) == 0) sh[threadIdx.x >> 5] = v;
    __syncthreads();
    if (threadIdx.x < 32) {
        float x = (threadIdx.x < NT / 32) ? sh[threadIdx.x] : 0.f;
        #pragma unroll
        for (int o = 16; o; o >>= 1) x += __shfl_xor_sync(0xffffffffu, x, o);
        if (threadIdx.x == 0) sh[0] = x;
    }
    __syncthreads();
    v = sh[0];
    __syncthreads();
    return v;
}

// ---------------- LayerNorm -> fp16 output ----------------
__global__ __launch_bounds__(128) void ln_kernel(
    const float* __restrict__ x, const float* __restrict__ gamma,
    const float* __restrict__ beta, __half* __restrict__ y)
{
    const float* xr = x + (size_t)blockIdx.x * DIM;
    __half* yr = y + (size_t)blockIdx.x * DIM;
    float v[4];
    float s = 0.f;
    #pragma unroll
    for (int i = 0; i < 4; i++) { v[i] = xr[threadIdx.x + 128 * i]; s += v[i]; }
    float mu = block_sum<128>(s) * (1.f / DIM);
    float var = 0.f;
    #pragma unroll
    for (int i = 0; i < 4; i++) { float d = v[i] - mu; var += d * d; }
    var = block_sum<128>(var) * (1.f / DIM);
    float r = rsqrtf(var + LNEPS);
    #pragma unroll
    for (int i = 0; i < 4; i++) {
        int c = threadIdx.x + 128 * i;
        yr[c] = __float2half((v[i] - mu) * r * gamma[c] + beta[c]);
    }
}

// ======== wmma GEMM 128x128, 8 warps (KV projection) ========
template<bool OUT_HALF>
__global__ __launch_bounds__(256, 2) void gemm_wmma(
    const __half* __restrict__ A, const __half* __restrict__ B,
    const float* __restrict__ bias, void* __restrict__ Cv,
    int M, int N, int K)
{
    __shared__ __half As[128 * 40];
    __shared__ __half Bs[32 * 136];
    __shared__ float  stage[8][16 * 20];
    const int t = threadIdx.x, w = t >> 5, lane = t & 31;
    const int wr = w >> 1, wc = w & 1;
    const int i0 = blockIdx.y * 128, j0 = blockIdx.x * 128;
    wmma::fragment<wmma::accumulator, 16, 16, 16, float> acc[2][4];
    #pragma unroll
    for (int m = 0; m < 2; m++)
        #pragma unroll
        for (int n = 0; n < 4; n++) wmma::fill_fragment(acc[m][n], 0.f);

    for (int kt = 0; kt < K; kt += 32) {
        #pragma unroll
        for (int c = t; c < 512; c += 256) {
            int r = c >> 2, cc = (c & 3) << 3;
            *(uint4*)&As[r * 40 + cc] = *(const uint4*)&A[(size_t)(i0 + r) * K + kt + cc];
        }
        #pragma unroll
        for (int c = t; c < 512; c += 256) {
            int r = c >> 4, cc = (c & 15) << 3;
            *(uint4*)&Bs[r * 136 + cc] = *(const uint4*)&B[(size_t)(kt + r) * N + j0 + cc];
        }
        __syncthreads();
        #pragma unroll
        for (int kk = 0; kk < 2; kk++) {
            wmma::fragment<wmma::matrix_a, 16, 16, 16, __half, wmma::row_major> af[2];
            wmma::fragment<wmma::matrix_b, 16, 16, 16, __half, wmma::row_major> bf[4];
            #pragma unroll
            for (int m = 0; m < 2; m++)
                wmma::load_matrix_sync(af[m], &As[(wr * 32 + m * 16) * 40 + kk * 16], 40);
            #pragma unroll
            for (int n = 0; n < 4; n++)
                wmma::load_matrix_sync(bf[n], &Bs[(kk * 16) * 136 + wc * 64 + n * 16], 136);
            #pragma unroll
            for (int m = 0; m < 2; m++)
                #pragma unroll
                for (int n = 0; n < 4; n++)
                    wmma::mma_sync(acc[m][n], af[m], bf[n], acc[m][n]);
        }
        __syncthreads();
    }
    #pragma unroll
    for (int m = 0; m < 2; m++)
        #pragma unroll
        for (int n = 0; n < 4; n++) {
            wmma::store_matrix_sync(stage[w], acc[m][n], 20, wmma::mem_row_major);
            __syncwarp();
            int row = lane >> 1, c0 = (lane & 1) << 3;
            int gi = i0 + wr * 32 + m * 16 + row;
            int gj = j0 + wc * 64 + n * 16 + c0;
            #pragma unroll
            for (int c = 0; c < 8; c++) {
                float vv = stage[w][row * 20 + c0 + c] + bias[gj + c];
                if (OUT_HALF) ((__half*)Cv)[(size_t)gi * N + gj + c] = __float2half(vv);
                else          ((float*)Cv)[(size_t)gi * N + gj + c] = vv;
            }
            __syncwarp();
        }
}

// ======== wmma GEMM 64x64, 4 warps (Q/O projections) ========
template<bool OUT_HALF>
__global__ __launch_bounds__(128, 4) void gemm64_wmma(
    const __half* __restrict__ A, const __half* __restrict__ B,
    const float* __restrict__ bias, void* __restrict__ Cv,
    int M, int N, int K)
{
    __shared__ __half As[64 * 40];
    __shared__ __half Bs[32 * 72];
    __shared__ float  stage[4][16 * 20];
    const int t = threadIdx.x, w = t >> 5, lane = t & 31;
    const int wr = w >> 1, wc = w & 1;
    const int i0 = blockIdx.y * 64, j0 = blockIdx.x * 64;
    wmma::fragment<wmma::accumulator, 16, 16, 16, float> acc[2][2];
    #pragma unroll
    for (int m = 0; m < 2; m++)
        #pragma unroll
        for (int n = 0; n < 2; n++) wmma::fill_fragment(acc[m][n], 0.f);

    for (int kt = 0; kt < K; kt += 32) {
        #pragma unroll
        for (int c = t; c < 256; c += 128) {
            int r = c >> 2, cc = (c & 3) << 3;
            *(uint4*)&As[r * 40 + cc] = *(const uint4*)&A[(size_t)(i0 + r) * K + kt + cc];
        }
        #pragma unroll
        for (int c = t; c < 256; c += 128) {
            int r = c >> 3, cc = (c & 7) << 3;
            *(uint4*)&Bs[r * 72 + cc] = *(const uint4*)&B[(size_t)(kt + r) * N + j0 + cc];
        }
        __syncthreads();
        #pragma unroll
        for (int kk = 0; kk < 2; kk++) {
            wmma::fragment<wmma::matrix_a, 16, 16, 16, __half, wmma::row_major> af[2];
            wmma::fragment<wmma::matrix_b, 16, 16, 16, __half, wmma::row_major> bf[2];
            #pragma unroll
            for (int m = 0; m < 2; m++)
                wmma::load_matrix_sync(af[m], &As[(wr * 32 + m * 16) * 40 + kk * 16], 40);
            #pragma unroll
            for (int n = 0; n < 2; n++)
                wmma::load_matrix_sync(bf[n], &Bs[(kk * 16) * 72 + wc * 32 + n * 16], 72);
            #pragma unroll
            for (int m = 0; m < 2; m++)
                #pragma unroll
                for (int n = 0; n < 2; n++)
                    wmma::mma_sync(acc[m][n], af[m], bf[n], acc[m][n]);
        }
        __syncthreads();
    }
    #pragma unroll
    for (int m = 0; m < 2; m++)
        #pragma unroll
        for (int n = 0; n < 2; n++) {
            wmma::store_matrix_sync(stage[w], acc[m][n], 20, wmma::mem_row_major);
            __syncwarp();
            int row = lane >> 1, c0 = (lane & 1) << 3;
            int gi = i0 + wr * 32 + m * 16 + row;
            int gj = j0 + wc * 32 + n * 16 + c0;
            #pragma unroll
            for (int c = 0; c < 8; c++) {
                float vv = stage[w][row * 20 + c0 + c] + bias[gj + c];
                if (OUT_HALF) ((__half*)Cv)[(size_t)gi * N + gj + c] = __float2half(vv);
                else          ((float*)Cv)[(size_t)gi * N + gj + c] = vv;
            }
            __syncwarp();
        }
}

// ======== p = exp(scale * q kᵀ) per (b,h), fp16 out (max-free softmax) ======
__global__ __launch_bounds__(256, 2) void sim_wmma(
    const __half* __restrict__ q, const __half* __restrict__ kv,
    __half* __restrict__ p)
{
    __shared__ __half As[128 * 72];
    __shared__ __half Bs[128 * 72];
    __shared__ float  stage[8][16 * 20];
    const int bh = blockIdx.z, b = bh / NH, h = bh % NH;
    const __half* A  = q  + (size_t)b * NSINK * HID + h * HD;
    const __half* Bk = kv + (size_t)b * NSRC * (2 * HID) + h * HD;
    __half* C = p + (size_t)bh * NSINK * NSRC;
    const int t = threadIdx.x, w = t >> 5, lane = t & 31;
    const int wr = w >> 1, wc = w & 1;
    const int i0 = blockIdx.y * 128, j0 = blockIdx.x * 128;

    #pragma unroll
    for (int c = t; c < 1024; c += 256) {
        int r = c >> 3, cc = (c & 7) << 3;
        *(uint4*)&As[r * 72 + cc] = *(const uint4*)&A[(size_t)(i0 + r) * HID + cc];
    }
    #pragma unroll
    for (int c = t; c < 1024; c += 256) {
        int r = c >> 3, cc = (c & 7) << 3;
        *(uint4*)&Bs[r * 72 + cc] = *(const uint4*)&Bk[(size_t)(j0 + r) * (2 * HID) + cc];
    }
    __syncthreads();

    wmma::fragment<wmma::accumulator, 16, 16, 16, float> acc[2][4];
    #pragma unroll
    for (int m = 0; m < 2; m++)
        #pragma unroll
        for (int n = 0; n < 4; n++) wmma::fill_fragment(acc[m][n], 0.f);
    #pragma unroll
    for (int kk = 0; kk < 4; kk++) {
        wmma::fragment<wmma::matrix_a, 16, 16, 16, __half, wmma::row_major> af[2];
        wmma::fragment<wmma::matrix_b, 16, 16, 16, __half, wmma::col_major> bf[4];
        #pragma unroll
        for (int m = 0; m < 2; m++)
            wmma::load_matrix_sync(af[m], &As[(wr * 32 + m * 16) * 72 + kk * 16], 72);
        #pragma unroll
        for (int n = 0; n < 4; n++)
            wmma::load_matrix_sync(bf[n], &Bs[(wc * 64 + n * 16) * 72 + kk * 16], 72);
        #pragma unroll
        for (int m = 0; m < 2; m++)
            #pragma unroll
            for (int n = 0; n < 4; n++)
                wmma::mma_sync(acc[m][n], af[m], bf[n], acc[m][n]);
    }
    #pragma unroll
    for (int m = 0; m < 2; m++)
        #pragma unroll
        for (int n = 0; n < 4; n++) {
            wmma::store_matrix_sync(stage[w], acc[m][n], 20, wmma::mem_row_major);
            __syncwarp();
            int row = lane >> 1, c0 = (lane & 1) << 3;
            int gi = i0 + wr * 32 + m * 16 + row;
            int gj = j0 + wc * 64 + n * 16 + c0;
            #pragma unroll
            for (int c = 0; c < 8; c++)
                C[(size_t)gi * NSRC + gj + c] =
                    __float2half(__expf(stage[w][row * 20 + c0 + c] * 0.125f));
            __syncwarp();
        }
}

// ======== colsum partials: zpart[bh][chunk][j] = sum over 256 rows ========
__global__ __launch_bounds__(256) void colsum_part(
    const __half* __restrict__ p, float* __restrict__ zpart)
{
    const int bh = blockIdx.z, chunk = blockIdx.y;
    const int j = blockIdx.x * 512 + threadIdx.x * 2;
    const int irow0 = chunk * (NSINK / ICHUNKS);
    const __half* P = p + (size_t)bh * NSINK * NSRC + (size_t)irow0 * NSRC + j;
    float2 z0 = {0.f, 0.f}, z1 = {0.f, 0.f}, z2 = {0.f, 0.f}, z3 = {0.f, 0.f};
    #pragma unroll 1
    for (int i = 0; i < NSINK / ICHUNKS; i += 4) {
        float2 a = __half22float2(*(const __half2*)&P[(size_t)(i + 0) * NSRC]);
        float2 b = __half22float2(*(const __half2*)&P[(size_t)(i + 1) * NSRC]);
        float2 c = __half22float2(*(const __half2*)&P[(size_t)(i + 2) * NSRC]);
        float2 d = __half22float2(*(const __half2*)&P[(size_t)(i + 3) * NSRC]);
        z0.x += a.x; z0.y += a.y;
        z1.x += b.x; z1.y += b.y;
        z2.x += c.x; z2.y += c.y;
        z3.x += d.x; z3.y += d.y;
    }
    float* Z = zpart + ((size_t)bh * ICHUNKS + chunk) * NSRC;
    Z[j]     = z0.x + z1.x + z2.x + z3.x;
    Z[j + 1] = z0.y + z1.y + z2.y + z3.y;
}

// ======== reduce colsum partials -> colz = 1/z ========
__global__ __launch_bounds__(256) void reduce_colz(
    const float* __restrict__ zpart, float* __restrict__ colz)
{
    int idx = blockIdx.x * 256 + threadIdx.x;         // 16*4096 = 65536
    int bh = idx / NSRC, j = idx % NSRC;
    const float* Z = zpart + (size_t)bh * ICHUNKS * NSRC + j;
    colz[idx] = 1.f / (Z[0] + Z[NSRC] + Z[2 * NSRC] + Z[3 * NSRC]);
}

// ======== av partials: opart[chunk] += attn-chunk @ V_ext (fp32 out) ========
// grid (JCHUNKS, NSINK/64, BATCH*NH), 4 warps. 16 j-iters per block.
__global__ __launch_bounds__(128, 4) void av_wmma_part(
    const __half* __restrict__ p, const __half* __restrict__ kv,
    const float* __restrict__ colz, float* __restrict__ opart,
    float* __restrict__ rspart)
{
    __shared__ __half As[64 * 72];     // attn [i][j64] ld 72
    __shared__ __half Bs[64 * 88];     // V_ext [j][88] ld 88
    __shared__ float  stage[4][16 * 20];
    const int chunk = blockIdx.x;
    const int bh = blockIdx.z, b = bh / NH, h = bh % NH;
    const __half* A = p + (size_t)bh * NSINK * NSRC;
    const __half* V = kv + (size_t)b * NSRC * (2 * HID) + HID + h * HD;
    const float* cz = colz + bh * NSRC;
    const int t = threadIdx.x, w = t >> 5, lane = t & 31;
    const int i0 = blockIdx.y * 64;
    const int j0chunk = chunk * (NSRC / JCHUNKS);

    wmma::fragment<wmma::accumulator, 16, 16, 16, float> acc[5];
    #pragma unroll
    for (int n = 0; n < 5; n++) wmma::fill_fragment(acc[n], 0.f);

    for (int kt = j0chunk; kt < j0chunk + NSRC / JCHUNKS; kt += 64) {
        #pragma unroll
        for (int e = t; e < 2048; e += 128) {
            int r = e >> 5, c2 = e & 31;
            int j = kt + c2 * 2;
            float2 pf = __half22float2(*(const __half2*)&A[(size_t)(i0 + r) * NSRC + j]);
            float2 zf = *(const float2*)&cz[j];
            *(__half2*)&As[r * 72 + c2 * 2] =
                __floats2half2_rn(pf.x * zf.x + ATTEPS, pf.y * zf.y + ATTEPS);
        }
        #pragma unroll
        for (int c = t; c < 512; c += 128) {
            int r = c >> 3, cc = (c & 7) << 3;
            *(uint4*)&Bs[r * 88 + cc] = *(const uint4*)&V[(size_t)(kt + r) * (2 * HID) + cc];
        }
        #pragma unroll
        for (int e = t; e < 64 * 24; e += 128) {
            int r = e / 24, cc = 64 + e % 24;
            Bs[r * 88 + cc] = __float2half(cc == 64 ? 1.f : 0.f);
        }
        __syncthreads();
        #pragma unroll
        for (int kk = 0; kk < 4; kk++) {
            wmma::fragment<wmma::matrix_a, 16, 16, 16, __half, wmma::row_major> af;
            wmma::load_matrix_sync(af, &As[(w * 16) * 72 + kk * 16], 72);
            #pragma unroll
            for (int n = 0; n < 5; n++) {
                wmma::fragment<wmma::matrix_b, 16, 16, 16, __half, wmma::row_major> bf;
                wmma::load_matrix_sync(bf, &Bs[(kk * 16) * 88 + n * 16], 88);
                wmma::mma_sync(acc[n], af, bf, acc[n]);
            }
        }
        __syncthreads();
    }
    // rowsum partial from ones column (frag 4, local col 0)
    wmma::store_matrix_sync(stage[w], acc[4], 20, wmma::mem_row_major);
    __syncwarp();
    if (lane < 16)
        rspart[((size_t)chunk * BATCH * NH + bh) * NSINK + i0 + w * 16 + lane] =
            stage[w][lane * 20 + 0];
    __syncwarp();
    // fp32 output partial (no divide yet)
    float* OP = opart + (size_t)chunk * BATCH * NSINK * HID;
    #pragma unroll
    for (int n = 0; n < 4; n++) {
        wmma::store_matrix_sync(stage[w], acc[n], 20, wmma::mem_row_major);
        __syncwarp();
        int row = lane >> 1, c0 = (lane & 1) << 3;
        int gi = i0 + w * 16 + row;
        #pragma unroll
        for (int c = 0; c < 8; c++)
            OP[(size_t)(b * NSINK + gi) * HID + h * HD + n * 16 + c0 + c] =
                stage[w][row * 20 + c0 + c];
        __syncwarp();
    }
}

// ======== reduce av partials: o = (Σ opart) / (Σ rspart), fp16 out ========
__global__ __launch_bounds__(256) void reduce_av(
    const float* __restrict__ opart, const float* __restrict__ rspart,
    __half* __restrict__ o)
{
    int idx = blockIdx.x * 256 + threadIdx.x;         // BATCH*NSINK*HID = 1M
    int irow = idx / HID, col = idx % HID;
    int b = irow / NSINK, i = irow % NSINK;
    int bh = b * NH + (col >> 6);
    const size_t ostride = (size_t)BATCH * NSINK * HID;
    float v = opart[idx] + opart[idx + ostride] +
              opart[idx + 2 * ostride] + opart[idx + 3 * ostride];
    const size_t rstride = (size_t)BATCH * NH * NSINK;
    size_t r = (size_t)bh * NSINK + i;
    float rs = rspart[r] + rspart[r + rstride] +
               rspart[r + 2 * rstride] + rspart[r + 3 * rstride];
    o[idx] = __float2half(v / rs);
}

// ---------------- launch ----------------
extern "C" void kernel_launch(void* const* d_in, const int* in_sizes, int n_in,
                              void* d_out, int out_size)
{
    const float* sink    = (const float*)d_in[0];
    const float* source  = (const float*)d_in[1];
    const float* gamma_s = (const float*)d_in[2];
    const float* beta_s  = (const float*)d_in[3];
    const float* gamma_c = (const float*)d_in[4];
    const float* beta_c  = (const float*)d_in[5];
    const float* Wq      = (const float*)d_in[6];
    const float* bq      = (const float*)d_in[7];
    const float* Wkv     = (const float*)d_in[8];
    const float* bkv     = (const float*)d_in[9];
    const float* Wo      = (const float*)d_in[10];
    const float* bo      = (const float*)d_in[11];
    float* out = (float*)d_out;

    __half *snorm_h, *cnorm_h, *q_h, *kv_h, *p_h, *o_h, *wq_h, *wkv_h, *wo_h;
    float *zpart, *colz, *opart, *rspart;
    cudaGetSymbolAddress((void**)&snorm_h, g_snorm_h);
    cudaGetSymbolAddress((void**)&cnorm_h, g_cnorm_h);
    cudaGetSymbolAddress((void**)&q_h,     g_q_h);
    cudaGetSymbolAddress((void**)&kv_h,    g_kv_h);
    cudaGetSymbolAddress((void**)&p_h,     g_p_h);
    cudaGetSymbolAddress((void**)&zpart,   g_zpart);
    cudaGetSymbolAddress((void**)&colz,    g_colz);
    cudaGetSymbolAddress((void**)&opart,   g_opart);
    cudaGetSymbolAddress((void**)&rspart,  g_rspart);
    cudaGetSymbolAddress((void**)&o_h,     g_o_h);
    cudaGetSymbolAddress((void**)&wq_h,    g_wq_h);
    cudaGetSymbolAddress((void**)&wkv_h,   g_wkv_h);
    cudaGetSymbolAddress((void**)&wo_h,    g_wo_h);

    // 0. fused weight conversion
    cvt_all<<<4096, 256>>>(Wq, Wkv, Wo, wq_h, wkv_h, wo_h);

    // 1. pre-norms (fp16 out)
    ln_kernel<<<BATCH * NSINK, 128>>>(sink, gamma_s, beta_s, snorm_h);
    ln_kernel<<<BATCH * NSRC, 128>>>(source, gamma_c, beta_c, cnorm_h);

    // 2. projections
    gemm64_wmma<true><<<dim3(HID / 64, BATCH * NSINK / 64), 128>>>(
        snorm_h, wq_h, bq, q_h, BATCH * NSINK, HID, DIM);
    gemm_wmma<true><<<dim3(2 * HID / 128, BATCH * NSRC / 128), 256>>>(
        cnorm_h, wkv_h, bkv, kv_h, BATCH * NSRC, 2 * HID, DIM);

    // 3. p = exp(scale * q kᵀ)
    sim_wmma<<<dim3(NSRC / 128, NSINK / 128, BATCH * NH), 256>>>(q_h, kv_h, p_h);

    // 4. column sums (split-i x4) -> reduce -> 1/z
    colsum_part<<<dim3(NSRC / 512, ICHUNKS, BATCH * NH), 256>>>(p_h, zpart);
    reduce_colz<<<(BATCH * NH * NSRC) / 256, 256>>>(zpart, colz);

    // 5. AV partials (split-j x4, 1024 blocks) -> reduce with rowsum divide
    av_wmma_part<<<dim3(JCHUNKS, NSINK / 64, BATCH * NH), 128>>>(
        p_h, kv_h, colz, opart, rspart);
    reduce_av<<<(BATCH * NSINK * HID) / 256, 256>>>(opart, rspart, o_h);

    // 6. output projection (fp32 out)
    gemm64_wmma<false><<<dim3(DIM / 64, BATCH * NSINK / 64), 128>>>(
        o_h, wo_h, bo, out, BATCH * NSINK, DIM, DIM);
}